// round 8
// baseline (speedup 1.0000x reference)
#include <cuda_runtime.h>
#include <cuda_bf16.h>

// FM_12060268167845: factorization machine forward.
//   d_in[0] idx  i32 [B,K], d_in[1] x f32 [B,K], d_in[2] b f32 [B,K],
//   d_in[3] w f32 [1M,1], d_in[4] V f32 [1M,128], d_in[5] bias f32 [1]
// out f32 [B] = sigmoid(bias + Xw + 0.5/sum(x) * sum_f((XV)^2 - X2V2))
//
// v7: L2 temporal blocking. V (512MB) is split into NPASS=4 id-range slices
// of 128MB (~= L2 capacity). Four sequential kernel launches; pass p gathers
// only ids in slice p, so each slice's ~2x reuse is captured in L2 instead
// of refetched from DRAM (731MB -> ~600MB DRAM). Pass 0 bin-compacts each
// row's (off,x) list via warp ballots into scratch; passes 1..3 read only
// their dense segment. Per-row accumulators persist in __device__ scratch.
// Mainloop is the proven v3 shape: warp-per-row, lane owns 4 factors,
// U=8 front-batched warp-wide 512B LDG.128 bursts.

#define FM_B 8192
#define FM_K 200
#define FM_F 128
#define ROWS_PER_BLOCK 4
#define THREADS (ROWS_PER_BLOCK * 32)
#define U 8
#define NPASS 4
#define BIN_SHIFT 27            // byte-offset slice size = 2^27 = 128MB

struct __align__(8) OffX { unsigned off; float x; };

// Scratch (static __device__ allocations are allowed).
__device__ OffX   g_pairs[FM_B * FM_K];        // bin-sorted (off,x) per row
__device__ int    g_binoff[FM_B][NPASS + 1];   // bin segment starts
__device__ float4 g_a1[FM_B * 32];             // partial XV (lane-sliced)
__device__ float  g_a2[FM_B * 32];             // partial X2V2 (lane scalar)
__device__ float  g_xw[FM_B];
__device__ float  g_sx[FM_B];

__global__ __launch_bounds__(THREADS, 8)
void fm_pass(const int* __restrict__ idx,
             const float* __restrict__ x_vals,
             const float* __restrict__ b_vals,
             const float* __restrict__ w,
             const float* __restrict__ V,
             const float* __restrict__ bias,
             float* __restrict__ out,
             int pass)
{
    const int warp = threadIdx.x >> 5;
    const int lane = threadIdx.x & 31;
    const int b    = blockIdx.x * ROWS_PER_BLOCK + warp;
    const unsigned lt_mask = (1u << lane) - 1u;

    __shared__ OffX s_pairs[ROWS_PER_BLOCK][FM_K];
    __shared__ OffX s_raw[ROWS_PER_BLOCK][FM_K];

    const char* __restrict__ Vb = (const char*)V;
    const unsigned lane_off = (unsigned)lane << 4;

    float4 a1;
    float  a2s;
    int    m;                     // dense entries to process in s_pairs[0..m)

    if (pass == 0) {
        // ---- stage raw (off,x); fold linear term + sum(x) ----
        float xw = 0.0f, sx = 0.0f;
        const int base = b * FM_K;
        for (int k = lane; k < FM_K; k += 32) {
            int   id = idx[base + k];
            float xv = x_vals[base + k];
            OffX e; e.off = (unsigned)id * (FM_F * 4u); e.x = xv;
            s_raw[warp][k] = e;
            sx += xv;
            xw = fmaf(b_vals[base + k], __ldg(&w[id]), xw);
        }
        __syncwarp();

        // ---- sweep 1: per-bin totals (warp ballots) ----
        int cnt0 = 0, cnt1 = 0, cnt2 = 0, cnt3 = 0;
        for (int c = 0; c < FM_K; c += 32) {
            int k = c + lane;
            bool valid = (k < FM_K);
            unsigned bin = valid ? (s_raw[warp][k].off >> BIN_SHIFT) : 0xFFu;
            cnt0 += __popc(__ballot_sync(0xffffffffu, bin == 0u));
            cnt1 += __popc(__ballot_sync(0xffffffffu, bin == 1u));
            cnt2 += __popc(__ballot_sync(0xffffffffu, bin == 2u));
            cnt3 += __popc(__ballot_sync(0xffffffffu, bin == 3u));
        }
        int start[NPASS + 1];
        start[0] = 0;
        start[1] = cnt0;
        start[2] = cnt0 + cnt1;
        start[3] = cnt0 + cnt1 + cnt2;
        start[4] = cnt0 + cnt1 + cnt2 + cnt3;   // == FM_K

        // ---- sweep 2: compact-scatter into bin order ----
        int run0 = start[0], run1 = start[1], run2 = start[2], run3 = start[3];
        for (int c = 0; c < FM_K; c += 32) {
            int k = c + lane;
            bool valid = (k < FM_K);
            OffX e; e.off = 0u; e.x = 0.0f;
            if (valid) e = s_raw[warp][k];
            unsigned bin = valid ? (e.off >> BIN_SHIFT) : 0xFFu;

            unsigned m0 = __ballot_sync(0xffffffffu, bin == 0u);
            if (bin == 0u) s_pairs[warp][run0 + __popc(m0 & lt_mask)] = e;
            run0 += __popc(m0);
            unsigned m1 = __ballot_sync(0xffffffffu, bin == 1u);
            if (bin == 1u) s_pairs[warp][run1 + __popc(m1 & lt_mask)] = e;
            run1 += __popc(m1);
            unsigned m2 = __ballot_sync(0xffffffffu, bin == 2u);
            if (bin == 2u) s_pairs[warp][run2 + __popc(m2 & lt_mask)] = e;
            run2 += __popc(m2);
            unsigned m3 = __ballot_sync(0xffffffffu, bin == 3u);
            if (bin == 3u) s_pairs[warp][run3 + __popc(m3 & lt_mask)] = e;
            run3 += __popc(m3);
        }
        __syncwarp();

        // ---- persist bin layout + scalars ----
        if (lane <= NPASS) g_binoff[b][lane] = start[lane];
        for (int k = lane; k < FM_K; k += 32)
            g_pairs[b * FM_K + k] = s_pairs[warp][k];

        #pragma unroll
        for (int o = 16; o > 0; o >>= 1) {
            xw += __shfl_down_sync(0xffffffffu, xw, o);
            sx += __shfl_down_sync(0xffffffffu, sx, o);
        }
        if (lane == 0) { g_xw[b] = xw; g_sx[b] = sx; }

        a1  = make_float4(0.f, 0.f, 0.f, 0.f);
        a2s = 0.0f;
        m   = start[1];                  // bin 0 processed locally
    } else {
        int lo = g_binoff[b][pass];
        int hi = g_binoff[b][pass + 1];
        m = hi - lo;
        for (int k = lane; k < m; k += 32)
            s_pairs[warp][k] = g_pairs[b * FM_K + lo + k];
        __syncwarp();
        a1  = g_a1[b * 32 + lane];
        a2s = g_a2[b * 32 + lane];
    }

    // ---- dense v3-style mainloop over m entries ----
    const OffX* __restrict__ sp = s_pairs[warp];
    int k0 = 0;
    for (; k0 + U <= m; k0 += U) {
        float4 v[U];
        float  xr[U];
        #pragma unroll
        for (int u = 0; u < U; ++u) {
            OffX e = sp[k0 + u];
            xr[u] = e.x;
            v[u]  = __ldg((const float4*)(Vb + e.off + lane_off));
        }
        #pragma unroll
        for (int u = 0; u < U; ++u) {
            float x  = xr[u];
            float x2 = x * x;
            a1.x = fmaf(x, v[u].x, a1.x);
            a1.y = fmaf(x, v[u].y, a1.y);
            a1.z = fmaf(x, v[u].z, a1.z);
            a1.w = fmaf(x, v[u].w, a1.w);
            float n2 = fmaf(v[u].x, v[u].x,
                       fmaf(v[u].y, v[u].y,
                       fmaf(v[u].z, v[u].z, v[u].w * v[u].w)));
            a2s = fmaf(x2, n2, a2s);
        }
    }
    for (; k0 < m; ++k0) {
        OffX e = sp[k0];
        float4 vv = __ldg((const float4*)(Vb + e.off + lane_off));
        float x  = e.x;
        float x2 = x * x;
        a1.x = fmaf(x, vv.x, a1.x);
        a1.y = fmaf(x, vv.y, a1.y);
        a1.z = fmaf(x, vv.z, a1.z);
        a1.w = fmaf(x, vv.w, a1.w);
        float n2 = fmaf(vv.x, vv.x,
                   fmaf(vv.y, vv.y,
                   fmaf(vv.z, vv.z, vv.w * vv.w)));
        a2s = fmaf(x2, n2, a2s);
    }

    if (pass < NPASS - 1) {
        g_a1[b * 32 + lane] = a1;
        g_a2[b * 32 + lane] = a2s;
    } else {
        float pq = fmaf(a1.x, a1.x,
                   fmaf(a1.y, a1.y,
                   fmaf(a1.z, a1.z, a1.w * a1.w))) - a2s;
        #pragma unroll
        for (int o = 16; o > 0; o >>= 1)
            pq += __shfl_down_sync(0xffffffffu, pq, o);
        if (lane == 0) {
            float xw = g_xw[b];
            float sx = g_sx[b];
            float p  = 0.5f * (1.0f / sx) * pq;
            float logit = bias[0] + xw + p;
            out[b] = 1.0f / (1.0f + __expf(-logit));
        }
    }
}

extern "C" void kernel_launch(void* const* d_in, const int* in_sizes, int n_in,
                              void* d_out, int out_size)
{
    const int*   idx    = (const int*)d_in[0];
    const float* x_vals = (const float*)d_in[1];
    const float* b_vals = (const float*)d_in[2];
    const float* w      = (const float*)d_in[3];
    const float* V      = (const float*)d_in[4];
    const float* bias   = (const float*)d_in[5];
    float*       out    = (float*)d_out;
    (void)in_sizes; (void)n_in; (void)out_size;

    const int grid = FM_B / ROWS_PER_BLOCK;
    for (int p = 0; p < NPASS; ++p)
        fm_pass<<<grid, THREADS>>>(idx, x_vals, b_vals, w, V, bias, out, p);
}